// round 7
// baseline (speedup 1.0000x reference)
#include <cuda_runtime.h>
#include <cuda_bf16.h>
#include <cstdint>
#include <math.h>

#define N_ROWS 65536

// ======================= scratch (device globals) =======================
__device__ float         g_scal[(size_t)N_ROWS * 384];
__device__ __nv_bfloat16 g_scal_pl[2 * (size_t)N_ROWS * 384];   // hi/lo planes
__device__ __nv_bfloat16 g_h_pl[2 * (size_t)N_ROWS * 384];
__device__ float         g_g[(size_t)N_ROWS * 768];
__device__ float         g_s[(size_t)N_ROWS * 128];
__device__ float         g_v[(size_t)N_ROWS * 384];
__device__ __nv_bfloat16 g_w1t0[2 * 384 * 384];                 // [N,K] hi/lo planes
__device__ __nv_bfloat16 g_w2t0[2 * 384 * 768];
__device__ __nv_bfloat16 g_w1t1[2 * 384 * 384];
__device__ __nv_bfloat16 g_w2t1[2 * 384 * 768];

__device__ __forceinline__ float silu_f(float x) {
    return x / (1.0f + __expf(-x));
}
__device__ __forceinline__ void split_bf16(float x, __nv_bfloat16& hi, __nv_bfloat16& lo) {
    hi = __float2bfloat16(x);
    lo = __float2bfloat16(x - __bfloat162float(hi));
}

// ======================= PTX helpers (sm_100-baseline only) =======================
__device__ __forceinline__ uint32_t smem_u32(const void* p) {
    uint32_t a;
    asm("{ .reg .u64 t; cvta.to.shared.u64 t, %1; cvt.u32.u64 %0, t; }" : "=r"(a) : "l"(p));
    return a;
}
__device__ __forceinline__ void cp16(uint32_t dst, const void* src) {
    asm volatile("cp.async.cg.shared.global [%0], [%1], 16;" :: "r"(dst), "l"(src));
}
#define CP_COMMIT() asm volatile("cp.async.commit_group;" ::: "memory")
template<int NWAIT> __device__ __forceinline__ void cp_wait() {
    asm volatile("cp.async.wait_group %0;" :: "n"(NWAIT) : "memory");
}
__device__ __forceinline__ void ldsm_x4(uint32_t (&r)[4], uint32_t addr) {
    asm volatile("ldmatrix.sync.aligned.m8n8.x4.shared.b16 {%0,%1,%2,%3}, [%4];"
                 : "=r"(r[0]), "=r"(r[1]), "=r"(r[2]), "=r"(r[3]) : "r"(addr));
}
__device__ __forceinline__ void mma_bf16(float (&d)[4], const uint32_t (&a)[4],
                                         uint32_t b0, uint32_t b1) {
    asm volatile("mma.sync.aligned.m16n8k16.row.col.f32.bf16.bf16.f32 "
                 "{%0,%1,%2,%3}, {%4,%5,%6,%7}, {%8,%9}, {%0,%1,%2,%3};"
                 : "+f"(d[0]), "+f"(d[1]), "+f"(d[2]), "+f"(d[3])
                 : "r"(a[0]), "r"(a[1]), "r"(a[2]), "r"(a[3]), "r"(b0), "r"(b1));
}

// ======================= weight prep: fp32 [K,N] -> bf16 hi/lo planes [N,K] =======================
__global__ void prep_w(const float* __restrict__ W, int Kd, int Nd, __nv_bfloat16* __restrict__ out) {
    int idx = blockIdx.x * blockDim.x + threadIdx.x;
    if (idx >= Kd * Nd) return;
    int k = idx / Nd, n = idx % Nd;
    __nv_bfloat16 hi, lo;
    split_bf16(W[idx], hi, lo);
    out[(size_t)n * Kd + k] = hi;
    out[(size_t)Kd * Nd + (size_t)n * Kd + k] = lo;
}

// ======================= build scal (fp32 + planes) =======================
__global__ void build_scal2(const float* __restrict__ sp, int ss,
                            const float* __restrict__ vp, int vs,
                            float* __restrict__ scal, __nv_bfloat16* __restrict__ spl)
{
    const size_t PLS = (size_t)N_ROWS * 384;
    int idx = blockIdx.x * blockDim.x + threadIdx.x;
    int n = idx >> 7;
    int j = idx & 127;
    float s = sp[(size_t)n * ss + j];
    const float* vr = vp + (size_t)n * vs + 3 * j;
    float vx = vr[0], vy = vr[1], vz = vr[2];
    float vals[3];
    vals[0] = s;
    vals[1] = s * s;
    vals[2] = (vx*vx + vy*vy + vz*vz) * 0.5773502691896258f;
    float* row = scal + (size_t)n * 384;
    __nv_bfloat16* prow = spl + (size_t)n * 384;
#pragma unroll
    for (int q = 0; q < 3; q++) {
        int col = q * 128 + j;
        row[col] = vals[q];
        __nv_bfloat16 hi, lo;
        split_bf16(vals[q], hi, lo);
        prow[col] = hi;
        prow[PLS + col] = lo;
    }
}

// ======================= mma.sync bf16 split GEMM =======================
// C[row0:+128, n0:+128] = silu(scale * sum_3passes(Apl @ Wpl^T))
// Tile 128x128, 8 warps (2x4), warp tile 64x32, k-slab 64 bf16, 3-stage cp.async ring.
// SMEM rows are 128B with XOR-16B swizzle keyed on row index (conflict-free ldmatrix).
// OMODE 0: write bf16 hi/lo planes.  OMODE 1: write fp32.
#define STAGE_BYTES 32768
#define SMEM_MMA (3 * STAGE_BYTES)

__device__ __forceinline__ void load_tile_row(uint32_t dst_base, const char* src, int t) {
    const uint32_t xr = (uint32_t)(t & 7) << 4;
#pragma unroll
    for (int ch = 0; ch < 8; ch++) {
        uint32_t dst = dst_base + (uint32_t)t * 128u + (((uint32_t)ch * 16u) ^ xr);
        cp16(dst, src + ch * 16);
    }
}

template<int OMODE>
__global__ void __launch_bounds__(256, 1)
gemm_mma(const __nv_bfloat16* __restrict__ Apl, size_t a_ps,
         const __nv_bfloat16* __restrict__ Wpl, size_t w_ps,
         float* __restrict__ outf, __nv_bfloat16* __restrict__ outpl, size_t out_ps,
         int K, int NOUT, float scale)
{
    extern __shared__ __align__(1024) char smem[];
    const uint32_t sb = smem_u32(smem);
    const int tid    = threadIdx.x;
    const int lane   = tid & 31;
    const int wid    = tid >> 5;
    const int warp_m = wid >> 2;        // 0..1
    const int warp_n = wid & 3;         // 0..3
    const int row0   = blockIdx.y * 128;
    const int n0     = blockIdx.x * 128;
    const int KC     = K / 64;          // chunks per pass (6)
    const int P      = 3 * KC;          // total chunks (18)

    float acc[4][4][4];
#pragma unroll
    for (int i = 0; i < 4; i++)
#pragma unroll
        for (int j = 0; j < 4; j++)
#pragma unroll
            for (int q = 0; q < 4; q++) acc[i][j][q] = 0.0f;

    auto issue_chunk = [&](int c) {
        int pass = c / KC, kc = c - pass * KC;
        uint32_t st = sb + (uint32_t)(c % 3) * STAGE_BYTES;
        if (tid < 128) {
            const __nv_bfloat16* Ap = Apl + (pass == 2 ? a_ps : 0)
                                    + (size_t)(row0 + tid) * K + kc * 64;
            load_tile_row(st, (const char*)Ap, tid);
        } else {
            int t = tid - 128;
            const __nv_bfloat16* Wp = Wpl + (pass == 1 ? w_ps : 0)
                                    + (size_t)(n0 + t) * K + kc * 64;
            load_tile_row(st + 16384u, (const char*)Wp, t);
        }
    };

    issue_chunk(0); CP_COMMIT();
    issue_chunk(1); CP_COMMIT();

    const uint32_t khalf = ((uint32_t)(lane >> 4)) << 4;   // 0 or 16

    for (int c = 0; c < P; c++) {
        __syncthreads();                 // stage (c+2)%3 == (c-1)%3 free (compute c-1 done)
        if (c + 2 < P) issue_chunk(c + 2);
        CP_COMMIT();
        cp_wait<2>();                    // chunk c landed (this thread)
        __syncthreads();                 // chunk c landed (all threads)

        const uint32_t stA = sb + (uint32_t)(c % 3) * STAGE_BYTES;
        const uint32_t stB = stA + 16384u;

#pragma unroll
        for (int ks = 0; ks < 4; ks++) {
            const uint32_t kb = (uint32_t)ks * 32u + khalf;
            uint32_t a[4][4];
#pragma unroll
            for (int mi = 0; mi < 4; mi++) {
                uint32_t row  = (uint32_t)(warp_m * 64 + mi * 16 + (lane & 15));
                uint32_t addr = stA + row * 128u + (kb ^ ((row & 7) << 4));
                ldsm_x4(a[mi], addr);
            }
            uint32_t b[2][4];
#pragma unroll
            for (int pi = 0; pi < 2; pi++) {
                uint32_t row  = (uint32_t)(warp_n * 32 + pi * 16 + (lane & 15));
                uint32_t addr = stB + row * 128u + (kb ^ ((row & 7) << 4));
                ldsm_x4(b[pi], addr);
            }
#pragma unroll
            for (int mi = 0; mi < 4; mi++)
#pragma unroll
                for (int nj = 0; nj < 4; nj++)
                    mma_bf16(acc[mi][nj], a[mi], b[nj >> 1][nj & 1], b[nj >> 1][(nj & 1) + 2]);
        }
    }

    // ---- epilogue ----
    const int rbase = row0 + warp_m * 64 + (lane >> 2);
    const int cbase = n0 + warp_n * 32 + (lane & 3) * 2;
#pragma unroll
    for (int mi = 0; mi < 4; mi++) {
#pragma unroll
        for (int nj = 0; nj < 4; nj++) {
            const int col = cbase + nj * 8;
            const int r0  = rbase + mi * 16;
            const int r1  = r0 + 8;
            float v0 = silu_f(acc[mi][nj][0] * scale);
            float v1 = silu_f(acc[mi][nj][1] * scale);
            float v2 = silu_f(acc[mi][nj][2] * scale);
            float v3 = silu_f(acc[mi][nj][3] * scale);
            if (OMODE == 0) {
                __nv_bfloat16 h0, l0, h1, l1, h2, l2, h3, l3;
                split_bf16(v0, h0, l0); split_bf16(v1, h1, l1);
                split_bf16(v2, h2, l2); split_bf16(v3, h3, l3);
                __nv_bfloat16* hi = outpl;
                __nv_bfloat16* lo = outpl + out_ps;
                __nv_bfloat162 p;
                p.x = h0; p.y = h1; *reinterpret_cast<__nv_bfloat162*>(hi + (size_t)r0 * NOUT + col) = p;
                p.x = l0; p.y = l1; *reinterpret_cast<__nv_bfloat162*>(lo + (size_t)r0 * NOUT + col) = p;
                p.x = h2; p.y = h3; *reinterpret_cast<__nv_bfloat162*>(hi + (size_t)r1 * NOUT + col) = p;
                p.x = l2; p.y = l3; *reinterpret_cast<__nv_bfloat162*>(lo + (size_t)r1 * NOUT + col) = p;
            } else {
                float2 q;
                q.x = v0; q.y = v1; *reinterpret_cast<float2*>(outf + (size_t)r0 * NOUT + col) = q;
                q.x = v2; q.y = v3; *reinterpret_cast<float2*>(outf + (size_t)r1 * NOUT + col) = q;
            }
        }
    }
}

// ======================= SIMT GEMM (modes 1 and 2) =======================
#define BM 128
#define BN 128
#define BK 8

template<int MODE>
__global__ __launch_bounds__(256, 2)
void gemm_tpl(const float* __restrict__ A, int lda,
              const float* __restrict__ G,
              const float* __restrict__ Vin, int ldv,
              const float* __restrict__ Sin, int lds_,
              const float* __restrict__ B,
              float* __restrict__ C, int ldc,
              int K, int M, float scale)
{
    __shared__ float As[BK][BM];
    __shared__ float Bs[BK][BN];

    const int tid  = threadIdx.x;
    const int row0 = blockIdx.y * BM;
    const int col0 = blockIdx.x * BN;
    const int c    = (MODE == 2) ? blockIdx.z : 0;

    const int ar = tid >> 1;
    const int ak = (tid & 1) * 4;
    const int br = tid >> 5;
    const int bc = (tid & 31) * 4;
    const int tx = tid & 15;
    const int ty = tid >> 4;

    float acc[8][8];
#pragma unroll
    for (int i = 0; i < 8; i++)
#pragma unroll
        for (int j = 0; j < 8; j++) acc[i][j] = 0.0f;

    const int arow = row0 + ar;

    for (int k0 = 0; k0 < K; k0 += BK) {
        float a[4];
        const int kk0 = k0 + ak;
        if (MODE == 1) {
            float4 av = *(const float4*)(A + (size_t)arow * lda + kk0);
            float4 gv = *(const float4*)(G + (size_t)arow * 768 + kk0);
            a[0] = av.x * gv.x; a[1] = av.y * gv.y;
            a[2] = av.z * gv.z; a[3] = av.w * gv.w;
        } else {
            const float* grow = G + (size_t)arow * 768 + 384;
#pragma unroll
            for (int q = 0; q < 4; q++) {
                int m = kk0 + q;
                float base;
                if (m < 128) {
                    base = Vin[(size_t)arow * ldv + m * 3 + c];
                } else {
                    int mm = m - 128;
                    base = Sin[(size_t)arow * lds_ + mm] *
                           Vin[(size_t)arow * ldv + mm * 3 + c];
                }
                a[q] = grow[m] * base;
            }
        }
        float4 bv = *(const float4*)(B + (size_t)(k0 + br) * M + col0 + bc);

        __syncthreads();
        As[ak + 0][ar] = a[0];
        As[ak + 1][ar] = a[1];
        As[ak + 2][ar] = a[2];
        As[ak + 3][ar] = a[3];
        *(float4*)&Bs[br][bc] = bv;
        __syncthreads();

#pragma unroll
        for (int kk = 0; kk < BK; kk++) {
            float ra[8], rb[8];
            float4 a0 = *(const float4*)&As[kk][ty * 8];
            float4 a1 = *(const float4*)&As[kk][ty * 8 + 4];
            ra[0]=a0.x; ra[1]=a0.y; ra[2]=a0.z; ra[3]=a0.w;
            ra[4]=a1.x; ra[5]=a1.y; ra[6]=a1.z; ra[7]=a1.w;
            float4 b0 = *(const float4*)&Bs[kk][tx * 4];
            float4 b1 = *(const float4*)&Bs[kk][64 + tx * 4];
            rb[0]=b0.x; rb[1]=b0.y; rb[2]=b0.z; rb[3]=b0.w;
            rb[4]=b1.x; rb[5]=b1.y; rb[6]=b1.z; rb[7]=b1.w;
#pragma unroll
            for (int i = 0; i < 8; i++)
#pragma unroll
                for (int j = 0; j < 8; j++)
                    acc[i][j] = fmaf(ra[i], rb[j], acc[i][j]);
        }
    }

#pragma unroll
    for (int i = 0; i < 8; i++) {
        const int r = row0 + ty * 8 + i;
        if (MODE == 1) {
            float4 s0 = *(const float4*)(Sin + (size_t)r * lds_ + col0 + tx * 4);
            float4 s1 = *(const float4*)(Sin + (size_t)r * lds_ + col0 + 64 + tx * 4);
            float4 o0, o1;
            o0.x = s0.x + acc[i][0]*scale; o0.y = s0.y + acc[i][1]*scale;
            o0.z = s0.z + acc[i][2]*scale; o0.w = s0.w + acc[i][3]*scale;
            o1.x = s1.x + acc[i][4]*scale; o1.y = s1.y + acc[i][5]*scale;
            o1.z = s1.z + acc[i][6]*scale; o1.w = s1.w + acc[i][7]*scale;
            *(float4*)(C + (size_t)r * ldc + col0 + tx * 4)      = o0;
            *(float4*)(C + (size_t)r * ldc + col0 + 64 + tx * 4) = o1;
        } else {
#pragma unroll
            for (int j = 0; j < 8; j++) {
                int cc = col0 + tx * 4 + (j & 3) + (j >> 2) * 64;
                float res = Vin[(size_t)r * ldv + cc * 3 + c];
                C[(size_t)r * ldc + cc * 3 + c] = res + acc[i][j] * scale;
            }
        }
    }
}

// ======================= equivariant layernorm =======================
__device__ __forceinline__ float block_sum_128(float x, float* red)
{
#pragma unroll
    for (int o = 16; o; o >>= 1) x += __shfl_xor_sync(0xffffffffu, x, o);
    int t = threadIdx.x;
    if ((t & 31) == 0) red[t >> 5] = x;
    __syncthreads();
    float tot = red[0] + red[1] + red[2] + red[3];
    __syncthreads();
    return tot;
}

__global__ void ln_kernel(float* __restrict__ s, float* __restrict__ v)
{
    __shared__ float red[4];
    int n = blockIdx.x;
    int t = threadIdx.x;

    float sv = s[(size_t)n * 128 + t];
    float* vr = v + (size_t)n * 384 + 3 * t;
    float vx = vr[0], vy = vr[1], vz = vr[2];

    float sum  = block_sum_128(sv, red);
    float sum2 = block_sum_128(sv * sv, red);
    float vsum = block_sum_128(vx*vx + vy*vy + vz*vz, red);

    float mu  = sum * (1.0f / 128.0f);
    float var = sum2 * (1.0f / 128.0f) - mu * mu;
    float inv_sd = rsqrtf(var + 1e-6f);
    s[(size_t)n * 128 + t] = (sv - mu) * inv_sd;

    float inv_vs = rsqrtf(vsum * (1.0f / 384.0f) + 1e-6f);
    vr[0] = vx * inv_vs;
    vr[1] = vy * inv_vs;
    vr[2] = vz * inv_vs;
}

// ======================= launcher =======================
extern "C" void kernel_launch(void* const* d_in, const int* in_sizes, int n_in,
                              void* d_out, int out_size)
{
    const float* x    = (const float*)d_in[0];
    const float* W1_0 = (const float*)d_in[3];
    const float* W2_0 = (const float*)d_in[4];
    const float* Ws_0 = (const float*)d_in[5];
    const float* Wv_0 = (const float*)d_in[6];
    const float* W1_1 = (const float*)d_in[7];
    const float* W2_1 = (const float*)d_in[8];
    const float* Ws_1 = (const float*)d_in[9];
    const float* Wv_1 = (const float*)d_in[10];
    float* out = (float*)d_out;

    static float *scal = nullptr, *g = nullptr, *s = nullptr, *v = nullptr;
    static __nv_bfloat16 *scal_pl = nullptr, *h_pl = nullptr;
    static __nv_bfloat16 *w1t0 = nullptr, *w2t0 = nullptr, *w1t1 = nullptr, *w2t1 = nullptr;
    if (!scal) {
        cudaGetSymbolAddress((void**)&scal,    g_scal);
        cudaGetSymbolAddress((void**)&scal_pl, g_scal_pl);
        cudaGetSymbolAddress((void**)&h_pl,    g_h_pl);
        cudaGetSymbolAddress((void**)&g,       g_g);
        cudaGetSymbolAddress((void**)&s,       g_s);
        cudaGetSymbolAddress((void**)&v,       g_v);
        cudaGetSymbolAddress((void**)&w1t0,    g_w1t0);
        cudaGetSymbolAddress((void**)&w2t0,    g_w2t0);
        cudaGetSymbolAddress((void**)&w1t1,    g_w1t1);
        cudaGetSymbolAddress((void**)&w2t1,    g_w2t1);
        cudaFuncSetAttribute(gemm_mma<0>, cudaFuncAttributeMaxDynamicSharedMemorySize, SMEM_MMA);
        cudaFuncSetAttribute(gemm_mma<1>, cudaFuncAttributeMaxDynamicSharedMemorySize, SMEM_MMA);
    }

    const float SC384 = 0.051031036307982884f;  // 1/sqrt(384)
    const float SC256 = 0.0625f;                // 1/sqrt(256)
    const int   RB    = N_ROWS / 128;           // 512 row tiles
    const size_t PLS  = (size_t)N_ROWS * 384;   // activation plane stride

    // weight prep (tiny)
    prep_w<<<(384*384 + 255)/256, 256>>>(W1_0, 384, 384, w1t0);
    prep_w<<<(384*768 + 255)/256, 256>>>(W2_0, 384, 768, w2t0);
    prep_w<<<(384*384 + 255)/256, 256>>>(W1_1, 384, 384, w1t1);
    prep_w<<<(384*768 + 255)/256, 256>>>(W2_1, 384, 768, w2t1);

    // ================= block 0 =================
    build_scal2<<<N_ROWS * 128 / 256, 256>>>(x, 512, x + 128, 512, scal, scal_pl);
    gemm_mma<0><<<dim3(3, RB), 256, SMEM_MMA>>>(scal_pl, PLS, w1t0, (size_t)384*384,
                                                nullptr, h_pl, PLS, 384, 384, SC384);
    gemm_mma<1><<<dim3(6, RB), 256, SMEM_MMA>>>(h_pl, PLS, w2t0, (size_t)384*768,
                                                g, nullptr, 0, 384, 768, SC384);
    gemm_tpl<1><<<dim3(1, RB), 256>>>(scal, 384, g, nullptr, 0, x, 512,
                                      Ws_0, s, 128, 384, 128, SC384);
    gemm_tpl<2><<<dim3(1, RB, 3), 256>>>(nullptr, 0, g, x + 128, 512, x, 512,
                                         Wv_0, v, 384, 256, 128, SC256);
    ln_kernel<<<N_ROWS, 128>>>(s, v);

    // ================= block 1 =================
    build_scal2<<<N_ROWS * 128 / 256, 256>>>(s, 128, v, 384, scal, scal_pl);
    gemm_mma<0><<<dim3(3, RB), 256, SMEM_MMA>>>(scal_pl, PLS, w1t1, (size_t)384*384,
                                                nullptr, h_pl, PLS, 384, 384, SC384);
    gemm_mma<1><<<dim3(6, RB), 256, SMEM_MMA>>>(h_pl, PLS, w2t1, (size_t)384*768,
                                                g, nullptr, 0, 384, 768, SC384);
    gemm_tpl<1><<<dim3(1, RB), 256>>>(scal, 384, g, nullptr, 0, s, 128,
                                      Ws_1, out, 512, 384, 128, SC384);
    gemm_tpl<2><<<dim3(1, RB, 3), 256>>>(nullptr, 0, g, v, 384, s, 128,
                                         Wv_1, out + 128, 512, 256, 128, SC256);
}

// round 8
// speedup vs baseline: 1.3319x; 1.3319x over previous
#include <cuda_runtime.h>
#include <cuda_bf16.h>
#include <cstdint>
#include <math.h>

#define N_ROWS 65536

// ======================= scratch (device globals) =======================
__device__ float         g_scal[(size_t)N_ROWS * 384];
__device__ __nv_bfloat16 g_scal_pl[2 * (size_t)N_ROWS * 384];   // hi/lo planes
__device__ __nv_bfloat16 g_h_pl[2 * (size_t)N_ROWS * 384];
__device__ float         g_g[(size_t)N_ROWS * 768];
__device__ float         g_s[(size_t)N_ROWS * 128];
__device__ float         g_v[(size_t)N_ROWS * 384];
__device__ __nv_bfloat16 g_w1t0[2 * 384 * 384];                 // [N,K] hi/lo planes
__device__ __nv_bfloat16 g_w2t0[2 * 384 * 768];
__device__ __nv_bfloat16 g_w1t1[2 * 384 * 384];
__device__ __nv_bfloat16 g_w2t1[2 * 384 * 768];

__device__ __forceinline__ float silu_f(float x) {
    return x / (1.0f + __expf(-x));
}
__device__ __forceinline__ void split_bf16(float x, __nv_bfloat16& hi, __nv_bfloat16& lo) {
    hi = __float2bfloat16(x);
    lo = __float2bfloat16(x - __bfloat162float(hi));
}

// ======================= PTX helpers (sm_100-baseline only) =======================
__device__ __forceinline__ uint32_t smem_u32(const void* p) {
    uint32_t a;
    asm("{ .reg .u64 t; cvta.to.shared.u64 t, %1; cvt.u32.u64 %0, t; }" : "=r"(a) : "l"(p));
    return a;
}
__device__ __forceinline__ void cp16(uint32_t dst, const void* src) {
    asm volatile("cp.async.cg.shared.global [%0], [%1], 16;" :: "r"(dst), "l"(src));
}
#define CP_COMMIT() asm volatile("cp.async.commit_group;" ::: "memory")
template<int NWAIT> __device__ __forceinline__ void cp_wait() {
    asm volatile("cp.async.wait_group %0;" :: "n"(NWAIT) : "memory");
}
__device__ __forceinline__ void ldsm_x4(uint32_t (&r)[4], uint32_t addr) {
    asm volatile("ldmatrix.sync.aligned.m8n8.x4.shared.b16 {%0,%1,%2,%3}, [%4];"
                 : "=r"(r[0]), "=r"(r[1]), "=r"(r[2]), "=r"(r[3]) : "r"(addr));
}
__device__ __forceinline__ void mma_bf16(float (&d)[4], const uint32_t (&a)[4],
                                         uint32_t b0, uint32_t b1) {
    asm volatile("mma.sync.aligned.m16n8k16.row.col.f32.bf16.bf16.f32 "
                 "{%0,%1,%2,%3}, {%4,%5,%6,%7}, {%8,%9}, {%0,%1,%2,%3};"
                 : "+f"(d[0]), "+f"(d[1]), "+f"(d[2]), "+f"(d[3])
                 : "r"(a[0]), "r"(a[1]), "r"(a[2]), "r"(a[3]), "r"(b0), "r"(b1));
}

// ======================= weight prep: fp32 [K,N] -> bf16 hi/lo planes [N,K] =======================
__global__ void prep_w(const float* __restrict__ W, int Kd, int Nd, __nv_bfloat16* __restrict__ out) {
    int idx = blockIdx.x * blockDim.x + threadIdx.x;
    if (idx >= Kd * Nd) return;
    int k = idx / Nd, n = idx % Nd;
    __nv_bfloat16 hi, lo;
    split_bf16(W[idx], hi, lo);
    out[(size_t)n * Kd + k] = hi;
    out[(size_t)Kd * Nd + (size_t)n * Kd + k] = lo;
}

// ======================= build scal (fp32 + planes) =======================
__global__ void build_scal2(const float* __restrict__ sp, int ss,
                            const float* __restrict__ vp, int vs,
                            float* __restrict__ scal, __nv_bfloat16* __restrict__ spl)
{
    const size_t PLS = (size_t)N_ROWS * 384;
    int idx = blockIdx.x * blockDim.x + threadIdx.x;
    int n = idx >> 7;
    int j = idx & 127;
    float s = sp[(size_t)n * ss + j];
    const float* vr = vp + (size_t)n * vs + 3 * j;
    float vx = vr[0], vy = vr[1], vz = vr[2];
    float vals[3];
    vals[0] = s;
    vals[1] = s * s;
    vals[2] = (vx*vx + vy*vy + vz*vz) * 0.5773502691896258f;
    float* row = scal + (size_t)n * 384;
    __nv_bfloat16* prow = spl + (size_t)n * 384;
#pragma unroll
    for (int q = 0; q < 3; q++) {
        int col = q * 128 + j;
        row[col] = vals[q];
        __nv_bfloat16 hi, lo;
        split_bf16(vals[q], hi, lo);
        prow[col] = hi;
        prow[PLS + col] = lo;
    }
}

// ======================= mma.sync bf16 split GEMM =======================
// C[row0:+128, n0:+128] = silu(scale * sum_3passes(Apl @ Wpl^T))
// Tile 128x128, 8 warps (2x4), warp tile 64x32, k-slab 64 bf16, 3-stage cp.async ring.
// SMEM rows 128B with XOR-16B swizzle keyed on row index (conflict-free ldmatrix).
// Loader: warp covers 4 consecutive rows x 128B -> fully coalesced (4 lines/instr).
// Pipeline: single __syncthreads per chunk; cp.async groups retire FIFO, so
// wait_group<1> (with an unconditional commit each iteration) proves chunk c landed.
// OMODE 0: write bf16 hi/lo planes.  OMODE 1: write fp32.
#define STAGE_BYTES 32768
#define SMEM_MMA (3 * STAGE_BYTES)

template<int OMODE>
__global__ void __launch_bounds__(256, 1)
gemm_mma(const __nv_bfloat16* __restrict__ Apl, size_t a_ps,
         const __nv_bfloat16* __restrict__ Wpl, size_t w_ps,
         float* __restrict__ outf, __nv_bfloat16* __restrict__ outpl, size_t out_ps,
         int K, int NOUT, float scale)
{
    extern __shared__ __align__(1024) char smem[];
    const uint32_t sb = smem_u32(smem);
    const int tid    = threadIdx.x;
    const int lane   = tid & 31;
    const int wid    = tid >> 5;
    const int warp_m = wid >> 2;        // 0..1
    const int warp_n = wid & 3;         // 0..3
    const int row0   = blockIdx.y * 128;
    const int n0     = blockIdx.x * 128;
    const int KC     = K / 64;          // chunks per pass (6)
    const int P      = 3 * KC;          // total chunks (18)
    const size_t rowbytes = (size_t)K * 2;

    float acc[4][4][4];
#pragma unroll
    for (int i = 0; i < 4; i++)
#pragma unroll
        for (int j = 0; j < 4; j++)
#pragma unroll
            for (int q = 0; q < 4; q++) acc[i][j][q] = 0.0f;

    // coalesced loader mapping (per half of the block)
    const int lt    = tid & 127;            // 0..127 within half
    const int tcol  = (lt & 7) * 16;        // byte column 0..112
    const int trow  = lt >> 3;              // 0..15
    const uint32_t sw = (uint32_t)(tcol ^ ((trow & 7) << 4));  // row&7 invariant under +16

    auto issue_chunk = [&](int c) {
        int pass = c / KC, kc = c - pass * KC;
        uint32_t st = sb + (uint32_t)(c % 3) * STAGE_BYTES;
        if (tid < 128) {
            const char* base = (const char*)(Apl + (pass == 2 ? a_ps : 0))
                             + (size_t)row0 * rowbytes + (size_t)kc * 128 + tcol;
#pragma unroll
            for (int j = 0; j < 8; j++) {
                int row = trow + j * 16;
                cp16(st + (uint32_t)row * 128u + sw, base + (size_t)row * rowbytes);
            }
        } else {
            const char* base = (const char*)(Wpl + (pass == 1 ? w_ps : 0))
                             + (size_t)n0 * rowbytes + (size_t)kc * 128 + tcol;
            uint32_t stb = st + 16384u;
#pragma unroll
            for (int j = 0; j < 8; j++) {
                int row = trow + j * 16;
                cp16(stb + (uint32_t)row * 128u + sw, base + (size_t)row * rowbytes);
            }
        }
    };

    issue_chunk(0); CP_COMMIT();
    issue_chunk(1); CP_COMMIT();

    const uint32_t khalf = ((uint32_t)(lane >> 4)) << 4;   // 0 or 16

    for (int c = 0; c < P; c++) {
        cp_wait<1>();                    // FIFO retirement => chunk c landed (mine)
        __syncthreads();                 // all threads waited => chunk c in smem;
                                         // also all finished compute c-1 (stage reuse safe)
        if (c + 2 < P) issue_chunk(c + 2);
        CP_COMMIT();                     // commit every iter (empty ok) -> stable indexing

        const uint32_t stA = sb + (uint32_t)(c % 3) * STAGE_BYTES;
        const uint32_t stB = stA + 16384u;

#pragma unroll
        for (int ks = 0; ks < 4; ks++) {
            const uint32_t kb = (uint32_t)ks * 32u + khalf;
            uint32_t a[4][4];
#pragma unroll
            for (int mi = 0; mi < 4; mi++) {
                uint32_t row  = (uint32_t)(warp_m * 64 + mi * 16 + (lane & 15));
                uint32_t addr = stA + row * 128u + (kb ^ ((row & 7) << 4));
                ldsm_x4(a[mi], addr);
            }
            uint32_t b[2][4];
#pragma unroll
            for (int pi = 0; pi < 2; pi++) {
                uint32_t row  = (uint32_t)(warp_n * 32 + pi * 16 + (lane & 15));
                uint32_t addr = stB + row * 128u + (kb ^ ((row & 7) << 4));
                ldsm_x4(b[pi], addr);
            }
#pragma unroll
            for (int mi = 0; mi < 4; mi++)
#pragma unroll
                for (int nj = 0; nj < 4; nj++)
                    mma_bf16(acc[mi][nj], a[mi], b[nj >> 1][nj & 1], b[nj >> 1][(nj & 1) + 2]);
        }
    }

    // ---- epilogue ----
    const int rbase = row0 + warp_m * 64 + (lane >> 2);
    const int cbase = n0 + warp_n * 32 + (lane & 3) * 2;
#pragma unroll
    for (int mi = 0; mi < 4; mi++) {
#pragma unroll
        for (int nj = 0; nj < 4; nj++) {
            const int col = cbase + nj * 8;
            const int r0  = rbase + mi * 16;
            const int r1  = r0 + 8;
            float v0 = silu_f(acc[mi][nj][0] * scale);
            float v1 = silu_f(acc[mi][nj][1] * scale);
            float v2 = silu_f(acc[mi][nj][2] * scale);
            float v3 = silu_f(acc[mi][nj][3] * scale);
            if (OMODE == 0) {
                __nv_bfloat16 h0, l0, h1, l1, h2, l2, h3, l3;
                split_bf16(v0, h0, l0); split_bf16(v1, h1, l1);
                split_bf16(v2, h2, l2); split_bf16(v3, h3, l3);
                __nv_bfloat16* hi = outpl;
                __nv_bfloat16* lo = outpl + out_ps;
                __nv_bfloat162 p;
                p.x = h0; p.y = h1; *reinterpret_cast<__nv_bfloat162*>(hi + (size_t)r0 * NOUT + col) = p;
                p.x = l0; p.y = l1; *reinterpret_cast<__nv_bfloat162*>(lo + (size_t)r0 * NOUT + col) = p;
                p.x = h2; p.y = h3; *reinterpret_cast<__nv_bfloat162*>(hi + (size_t)r1 * NOUT + col) = p;
                p.x = l2; p.y = l3; *reinterpret_cast<__nv_bfloat162*>(lo + (size_t)r1 * NOUT + col) = p;
            } else {
                float2 q;
                q.x = v0; q.y = v1; *reinterpret_cast<float2*>(outf + (size_t)r0 * NOUT + col) = q;
                q.x = v2; q.y = v3; *reinterpret_cast<float2*>(outf + (size_t)r1 * NOUT + col) = q;
            }
        }
    }
}

// ======================= SIMT GEMM (modes 1 and 2) =======================
#define BM 128
#define BN 128
#define BK 8

template<int MODE>
__global__ __launch_bounds__(256, 2)
void gemm_tpl(const float* __restrict__ A, int lda,
              const float* __restrict__ G,
              const float* __restrict__ Vin, int ldv,
              const float* __restrict__ Sin, int lds_,
              const float* __restrict__ B,
              float* __restrict__ C, int ldc,
              int K, int M, float scale)
{
    __shared__ float As[BK][BM];
    __shared__ float Bs[BK][BN];

    const int tid  = threadIdx.x;
    const int row0 = blockIdx.y * BM;
    const int col0 = blockIdx.x * BN;
    const int c    = (MODE == 2) ? blockIdx.z : 0;

    const int ar = tid >> 1;
    const int ak = (tid & 1) * 4;
    const int br = tid >> 5;
    const int bc = (tid & 31) * 4;
    const int tx = tid & 15;
    const int ty = tid >> 4;

    float acc[8][8];
#pragma unroll
    for (int i = 0; i < 8; i++)
#pragma unroll
        for (int j = 0; j < 8; j++) acc[i][j] = 0.0f;

    const int arow = row0 + ar;

    for (int k0 = 0; k0 < K; k0 += BK) {
        float a[4];
        const int kk0 = k0 + ak;
        if (MODE == 1) {
            float4 av = *(const float4*)(A + (size_t)arow * lda + kk0);
            float4 gv = *(const float4*)(G + (size_t)arow * 768 + kk0);
            a[0] = av.x * gv.x; a[1] = av.y * gv.y;
            a[2] = av.z * gv.z; a[3] = av.w * gv.w;
        } else {
            const float* grow = G + (size_t)arow * 768 + 384;
#pragma unroll
            for (int q = 0; q < 4; q++) {
                int m = kk0 + q;
                float base;
                if (m < 128) {
                    base = Vin[(size_t)arow * ldv + m * 3 + c];
                } else {
                    int mm = m - 128;
                    base = Sin[(size_t)arow * lds_ + mm] *
                           Vin[(size_t)arow * ldv + mm * 3 + c];
                }
                a[q] = grow[m] * base;
            }
        }
        float4 bv = *(const float4*)(B + (size_t)(k0 + br) * M + col0 + bc);

        __syncthreads();
        As[ak + 0][ar] = a[0];
        As[ak + 1][ar] = a[1];
        As[ak + 2][ar] = a[2];
        As[ak + 3][ar] = a[3];
        *(float4*)&Bs[br][bc] = bv;
        __syncthreads();

#pragma unroll
        for (int kk = 0; kk < BK; kk++) {
            float ra[8], rb[8];
            float4 a0 = *(const float4*)&As[kk][ty * 8];
            float4 a1 = *(const float4*)&As[kk][ty * 8 + 4];
            ra[0]=a0.x; ra[1]=a0.y; ra[2]=a0.z; ra[3]=a0.w;
            ra[4]=a1.x; ra[5]=a1.y; ra[6]=a1.z; ra[7]=a1.w;
            float4 b0 = *(const float4*)&Bs[kk][tx * 4];
            float4 b1 = *(const float4*)&Bs[kk][64 + tx * 4];
            rb[0]=b0.x; rb[1]=b0.y; rb[2]=b0.z; rb[3]=b0.w;
            rb[4]=b1.x; rb[5]=b1.y; rb[6]=b1.z; rb[7]=b1.w;
#pragma unroll
            for (int i = 0; i < 8; i++)
#pragma unroll
                for (int j = 0; j < 8; j++)
                    acc[i][j] = fmaf(ra[i], rb[j], acc[i][j]);
        }
    }

#pragma unroll
    for (int i = 0; i < 8; i++) {
        const int r = row0 + ty * 8 + i;
        if (MODE == 1) {
            float4 s0 = *(const float4*)(Sin + (size_t)r * lds_ + col0 + tx * 4);
            float4 s1 = *(const float4*)(Sin + (size_t)r * lds_ + col0 + 64 + tx * 4);
            float4 o0, o1;
            o0.x = s0.x + acc[i][0]*scale; o0.y = s0.y + acc[i][1]*scale;
            o0.z = s0.z + acc[i][2]*scale; o0.w = s0.w + acc[i][3]*scale;
            o1.x = s1.x + acc[i][4]*scale; o1.y = s1.y + acc[i][5]*scale;
            o1.z = s1.z + acc[i][6]*scale; o1.w = s1.w + acc[i][7]*scale;
            *(float4*)(C + (size_t)r * ldc + col0 + tx * 4)      = o0;
            *(float4*)(C + (size_t)r * ldc + col0 + 64 + tx * 4) = o1;
        } else {
#pragma unroll
            for (int j = 0; j < 8; j++) {
                int cc = col0 + tx * 4 + (j & 3) + (j >> 2) * 64;
                float res = Vin[(size_t)r * ldv + cc * 3 + c];
                C[(size_t)r * ldc + cc * 3 + c] = res + acc[i][j] * scale;
            }
        }
    }
}

// ======================= equivariant layernorm =======================
__device__ __forceinline__ float block_sum_128(float x, float* red)
{
#pragma unroll
    for (int o = 16; o; o >>= 1) x += __shfl_xor_sync(0xffffffffu, x, o);
    int t = threadIdx.x;
    if ((t & 31) == 0) red[t >> 5] = x;
    __syncthreads();
    float tot = red[0] + red[1] + red[2] + red[3];
    __syncthreads();
    return tot;
}

__global__ void ln_kernel(float* __restrict__ s, float* __restrict__ v)
{
    __shared__ float red[4];
    int n = blockIdx.x;
    int t = threadIdx.x;

    float sv = s[(size_t)n * 128 + t];
    float* vr = v + (size_t)n * 384 + 3 * t;
    float vx = vr[0], vy = vr[1], vz = vr[2];

    float sum  = block_sum_128(sv, red);
    float sum2 = block_sum_128(sv * sv, red);
    float vsum = block_sum_128(vx*vx + vy*vy + vz*vz, red);

    float mu  = sum * (1.0f / 128.0f);
    float var = sum2 * (1.0f / 128.0f) - mu * mu;
    float inv_sd = rsqrtf(var + 1e-6f);
    s[(size_t)n * 128 + t] = (sv - mu) * inv_sd;

    float inv_vs = rsqrtf(vsum * (1.0f / 384.0f) + 1e-6f);
    vr[0] = vx * inv_vs;
    vr[1] = vy * inv_vs;
    vr[2] = vz * inv_vs;
}

// ======================= launcher =======================
extern "C" void kernel_launch(void* const* d_in, const int* in_sizes, int n_in,
                              void* d_out, int out_size)
{
    const float* x    = (const float*)d_in[0];
    const float* W1_0 = (const float*)d_in[3];
    const float* W2_0 = (const float*)d_in[4];
    const float* Ws_0 = (const float*)d_in[5];
    const float* Wv_0 = (const float*)d_in[6];
    const float* W1_1 = (const float*)d_in[7];
    const float* W2_1 = (const float*)d_in[8];
    const float* Ws_1 = (const float*)d_in[9];
    const float* Wv_1 = (const float*)d_in[10];
    float* out = (float*)d_out;

    static float *scal = nullptr, *g = nullptr, *s = nullptr, *v = nullptr;
    static __nv_bfloat16 *scal_pl = nullptr, *h_pl = nullptr;
    static __nv_bfloat16 *w1t0 = nullptr, *w2t0 = nullptr, *w1t1 = nullptr, *w2t1 = nullptr;
    if (!scal) {
        cudaGetSymbolAddress((void**)&scal,    g_scal);
        cudaGetSymbolAddress((void**)&scal_pl, g_scal_pl);
        cudaGetSymbolAddress((void**)&h_pl,    g_h_pl);
        cudaGetSymbolAddress((void**)&g,       g_g);
        cudaGetSymbolAddress((void**)&s,       g_s);
        cudaGetSymbolAddress((void**)&v,       g_v);
        cudaGetSymbolAddress((void**)&w1t0,    g_w1t0);
        cudaGetSymbolAddress((void**)&w2t0,    g_w2t0);
        cudaGetSymbolAddress((void**)&w1t1,    g_w1t1);
        cudaGetSymbolAddress((void**)&w2t1,    g_w2t1);
        cudaFuncSetAttribute(gemm_mma<0>, cudaFuncAttributeMaxDynamicSharedMemorySize, SMEM_MMA);
        cudaFuncSetAttribute(gemm_mma<1>, cudaFuncAttributeMaxDynamicSharedMemorySize, SMEM_MMA);
    }

    const float SC384 = 0.051031036307982884f;  // 1/sqrt(384)
    const float SC256 = 0.0625f;                // 1/sqrt(256)
    const int   RB    = N_ROWS / 128;           // 512 row tiles
    const size_t PLS  = (size_t)N_ROWS * 384;   // activation plane stride

    // weight prep (tiny)
    prep_w<<<(384*384 + 255)/256, 256>>>(W1_0, 384, 384, w1t0);
    prep_w<<<(384*768 + 255)/256, 256>>>(W2_0, 384, 768, w2t0);
    prep_w<<<(384*384 + 255)/256, 256>>>(W1_1, 384, 384, w1t1);
    prep_w<<<(384*768 + 255)/256, 256>>>(W2_1, 384, 768, w2t1);

    // ================= block 0 =================
    build_scal2<<<N_ROWS * 128 / 256, 256>>>(x, 512, x + 128, 512, scal, scal_pl);
    gemm_mma<0><<<dim3(3, RB), 256, SMEM_MMA>>>(scal_pl, PLS, w1t0, (size_t)384*384,
                                                nullptr, h_pl, PLS, 384, 384, SC384);
    gemm_mma<1><<<dim3(6, RB), 256, SMEM_MMA>>>(h_pl, PLS, w2t0, (size_t)384*768,
                                                g, nullptr, 0, 384, 768, SC384);
    gemm_tpl<1><<<dim3(1, RB), 256>>>(scal, 384, g, nullptr, 0, x, 512,
                                      Ws_0, s, 128, 384, 128, SC384);
    gemm_tpl<2><<<dim3(1, RB, 3), 256>>>(nullptr, 0, g, x + 128, 512, x, 512,
                                         Wv_0, v, 384, 256, 128, SC256);
    ln_kernel<<<N_ROWS, 128>>>(s, v);

    // ================= block 1 =================
    build_scal2<<<N_ROWS * 128 / 256, 256>>>(s, 128, v, 384, scal, scal_pl);
    gemm_mma<0><<<dim3(3, RB), 256, SMEM_MMA>>>(scal_pl, PLS, w1t1, (size_t)384*384,
                                                nullptr, h_pl, PLS, 384, 384, SC384);
    gemm_mma<1><<<dim3(6, RB), 256, SMEM_MMA>>>(h_pl, PLS, w2t1, (size_t)384*768,
                                                g, nullptr, 0, 384, 768, SC384);
    gemm_tpl<1><<<dim3(1, RB), 256>>>(scal, 384, g, nullptr, 0, s, 128,
                                      Ws_1, out, 512, 384, 128, SC384);
    gemm_tpl<2><<<dim3(1, RB, 3), 256>>>(nullptr, 0, g, v, 384, s, 128,
                                         Wv_1, out + 128, 512, 256, 128, SC256);
}

// round 9
// speedup vs baseline: 1.3770x; 1.0339x over previous
#include <cuda_runtime.h>
#include <cuda_bf16.h>
#include <cstdint>
#include <math.h>

#define N_ROWS 65536

// ======================= scratch (device globals) =======================
__device__ float         g_scal[(size_t)N_ROWS * 384];
__device__ __nv_bfloat16 g_scal_pl[2 * (size_t)N_ROWS * 384];   // hi/lo planes
__device__ __nv_bfloat16 g_h_pl[2 * (size_t)N_ROWS * 384];
__device__ float         g_g[(size_t)N_ROWS * 768];
__device__ float         g_s[(size_t)N_ROWS * 128];
__device__ float         g_v[(size_t)N_ROWS * 384];
__device__ __nv_bfloat16 g_w1t0[2 * 384 * 384];                 // [N,K] hi/lo planes
__device__ __nv_bfloat16 g_w2t0[2 * 384 * 768];
__device__ __nv_bfloat16 g_w1t1[2 * 384 * 384];
__device__ __nv_bfloat16 g_w2t1[2 * 384 * 768];

__device__ __forceinline__ float silu_f(float x) {
    return x / (1.0f + __expf(-x));
}
__device__ __forceinline__ void split_bf16(float x, __nv_bfloat16& hi, __nv_bfloat16& lo) {
    hi = __float2bfloat16(x);
    lo = __float2bfloat16(x - __bfloat162float(hi));
}

// ======================= PTX helpers (sm_100-baseline only) =======================
__device__ __forceinline__ uint32_t smem_u32(const void* p) {
    uint32_t a;
    asm("{ .reg .u64 t; cvta.to.shared.u64 t, %1; cvt.u32.u64 %0, t; }" : "=r"(a) : "l"(p));
    return a;
}
__device__ __forceinline__ void cp16(uint32_t dst, const void* src) {
    asm volatile("cp.async.cg.shared.global [%0], [%1], 16;" :: "r"(dst), "l"(src));
}
#define CP_COMMIT() asm volatile("cp.async.commit_group;" ::: "memory")
template<int NWAIT> __device__ __forceinline__ void cp_wait() {
    asm volatile("cp.async.wait_group %0;" :: "n"(NWAIT) : "memory");
}
__device__ __forceinline__ void ldsm_x4(uint32_t (&r)[4], uint32_t addr) {
    asm volatile("ldmatrix.sync.aligned.m8n8.x4.shared.b16 {%0,%1,%2,%3}, [%4];"
                 : "=r"(r[0]), "=r"(r[1]), "=r"(r[2]), "=r"(r[3]) : "r"(addr));
}
__device__ __forceinline__ void mma_bf16(float (&d)[4], const uint32_t (&a)[4],
                                         uint32_t b0, uint32_t b1) {
    asm volatile("mma.sync.aligned.m16n8k16.row.col.f32.bf16.bf16.f32 "
                 "{%0,%1,%2,%3}, {%4,%5,%6,%7}, {%8,%9}, {%0,%1,%2,%3};"
                 : "+f"(d[0]), "+f"(d[1]), "+f"(d[2]), "+f"(d[3])
                 : "r"(a[0]), "r"(a[1]), "r"(a[2]), "r"(a[3]), "r"(b0), "r"(b1));
}

// ======================= weight prep: fp32 [K,N] -> bf16 hi/lo planes [N,K] =======================
__global__ void prep_w(const float* __restrict__ W, int Kd, int Nd, __nv_bfloat16* __restrict__ out) {
    int idx = blockIdx.x * blockDim.x + threadIdx.x;
    if (idx >= Kd * Nd) return;
    int k = idx / Nd, n = idx % Nd;
    __nv_bfloat16 hi, lo;
    split_bf16(W[idx], hi, lo);
    out[(size_t)n * Kd + k] = hi;
    out[(size_t)Kd * Nd + (size_t)n * Kd + k] = lo;
}

// ======================= build scal (fp32 + planes) =======================
__global__ void build_scal2(const float* __restrict__ sp, int ss,
                            const float* __restrict__ vp, int vs,
                            float* __restrict__ scal, __nv_bfloat16* __restrict__ spl)
{
    const size_t PLS = (size_t)N_ROWS * 384;
    int idx = blockIdx.x * blockDim.x + threadIdx.x;
    int n = idx >> 7;
    int j = idx & 127;
    float s = sp[(size_t)n * ss + j];
    const float* vr = vp + (size_t)n * vs + 3 * j;
    float vx = vr[0], vy = vr[1], vz = vr[2];
    float vals[3];
    vals[0] = s;
    vals[1] = s * s;
    vals[2] = (vx*vx + vy*vy + vz*vz) * 0.5773502691896258f;
    float* row = scal + (size_t)n * 384;
    __nv_bfloat16* prow = spl + (size_t)n * 384;
#pragma unroll
    for (int q = 0; q < 3; q++) {
        int col = q * 128 + j;
        row[col] = vals[q];
        __nv_bfloat16 hi, lo;
        split_bf16(vals[q], hi, lo);
        prow[col] = hi;
        prow[PLS + col] = lo;
    }
}

// ======================= mma.sync bf16 split GEMM =======================
// C[row0:+128, n0:+TILE_N] = silu(scale * sum_3passes(Apl @ Wpl^T))
// 8 warps (2x4), warp tile 64 x TILE_N/4, k-slab 64 bf16, 4-stage cp.async ring
// with 3 chunks in flight (wait_group<2>). SMEM rows 128B, XOR-16B swizzle on
// row index; unified coalesced loader (consecutive threads -> consecutive 16B).
// OMODE 0: write bf16 hi/lo planes.  OMODE 1: write fp32.
#define DEPTH 4

template<int TILE_N, int OMODE>
__global__ void __launch_bounds__(256, 1)
gemm_mma(const __nv_bfloat16* __restrict__ Apl, size_t a_ps,
         const __nv_bfloat16* __restrict__ Wpl, size_t w_ps,
         float* __restrict__ outf, __nv_bfloat16* __restrict__ outpl, size_t out_ps,
         int K, int NOUT, float scale)
{
    constexpr int NJ    = TILE_N / 32;          // 8-col groups per warp (4 or 8)
    constexpr int PI    = TILE_N / 64;          // B ldsm_x4 per ks (2 or 4)
    constexpr int STAGE = 16384 + TILE_N * 128; // bytes per stage
    constexpr int ROWS  = 128 + TILE_N;         // smem rows per stage
    constexpr int OPS   = ROWS * 8 / 256;       // cp16 per thread per chunk

    extern __shared__ __align__(1024) char smem[];
    const uint32_t sb = smem_u32(smem);
    const int tid    = threadIdx.x;
    const int lane   = tid & 31;
    const int wid    = tid >> 5;
    const int warp_m = wid >> 2;        // 0..1
    const int warp_n = wid & 3;         // 0..3
    const int row0   = blockIdx.y * 128;
    const int n0     = blockIdx.x * TILE_N;
    const int KC     = K / 64;          // chunks per pass (6)
    const int P      = 3 * KC;          // total chunks (18)
    const size_t rowbytes = (size_t)K * 2;

    float acc[4][NJ][4];
#pragma unroll
    for (int i = 0; i < 4; i++)
#pragma unroll
        for (int j = 0; j < NJ; j++)
#pragma unroll
            for (int q = 0; q < 4; q++) acc[i][j][q] = 0.0f;

    auto issue_chunk = [&](int c) {
        int pass = c / KC, kc = c - pass * KC;
        uint32_t st = sb + (uint32_t)(c % DEPTH) * STAGE;
        const char* Abase = (const char*)(Apl + (pass == 2 ? a_ps : 0))
                          + (size_t)row0 * rowbytes + (size_t)kc * 128;
        const char* Wbase = (const char*)(Wpl + (pass == 1 ? w_ps : 0))
                          + (size_t)n0 * rowbytes + (size_t)kc * 128;
#pragma unroll
        for (int j = 0; j < OPS; j++) {
            int o    = tid + 256 * j;
            int row  = o >> 3;
            int colb = (o & 7) * 16;
            uint32_t sw = (uint32_t)(colb ^ ((row & 7) << 4));
            const char* src = (row < 128)
                ? Abase + (size_t)row * rowbytes + colb
                : Wbase + (size_t)(row - 128) * rowbytes + colb;
            cp16(st + (uint32_t)row * 128u + sw, src);
        }
    };

    issue_chunk(0); CP_COMMIT();
    issue_chunk(1); CP_COMMIT();
    issue_chunk(2); CP_COMMIT();

    const uint32_t khalf = ((uint32_t)(lane >> 4)) << 4;   // 0 or 16

    for (int c = 0; c < P; c++) {
        cp_wait<2>();                    // FIFO: chunk c landed (mine)
        __syncthreads();                 // all threads: chunk c visible; compute c-1 done
        if (c + 3 < P) issue_chunk(c + 3);
        CP_COMMIT();                     // commit every iter -> stable group indexing

        const uint32_t stA = sb + (uint32_t)(c % DEPTH) * STAGE;
        const uint32_t stB = stA + 16384u;

#pragma unroll
        for (int ks = 0; ks < 4; ks++) {
            const uint32_t kb = (uint32_t)ks * 32u + khalf;
            uint32_t a[4][4];
#pragma unroll
            for (int mi = 0; mi < 4; mi++) {
                uint32_t row  = (uint32_t)(warp_m * 64 + mi * 16 + (lane & 15));
                uint32_t addr = stA + row * 128u + (kb ^ ((row & 7) << 4));
                ldsm_x4(a[mi], addr);
            }
            uint32_t b[PI][4];
#pragma unroll
            for (int pi = 0; pi < PI; pi++) {
                uint32_t row  = (uint32_t)(warp_n * (TILE_N / 4) + pi * 16 + (lane & 15));
                uint32_t addr = stB + row * 128u + (kb ^ ((row & 7) << 4));
                ldsm_x4(b[pi], addr);
            }
#pragma unroll
            for (int mi = 0; mi < 4; mi++)
#pragma unroll
                for (int nj = 0; nj < NJ; nj++)
                    mma_bf16(acc[mi][nj], a[mi], b[nj >> 1][nj & 1], b[nj >> 1][(nj & 1) + 2]);
        }
    }

    // ---- epilogue ----
    const int rbase = row0 + warp_m * 64 + (lane >> 2);
    const int cbase = n0 + warp_n * (TILE_N / 4) + (lane & 3) * 2;
#pragma unroll
    for (int mi = 0; mi < 4; mi++) {
#pragma unroll
        for (int nj = 0; nj < NJ; nj++) {
            const int col = cbase + nj * 8;
            const int r0  = rbase + mi * 16;
            const int r1  = r0 + 8;
            float v0 = silu_f(acc[mi][nj][0] * scale);
            float v1 = silu_f(acc[mi][nj][1] * scale);
            float v2 = silu_f(acc[mi][nj][2] * scale);
            float v3 = silu_f(acc[mi][nj][3] * scale);
            if (OMODE == 0) {
                __nv_bfloat16 h0, l0, h1, l1, h2, l2, h3, l3;
                split_bf16(v0, h0, l0); split_bf16(v1, h1, l1);
                split_bf16(v2, h2, l2); split_bf16(v3, h3, l3);
                __nv_bfloat16* hi = outpl;
                __nv_bfloat16* lo = outpl + out_ps;
                __nv_bfloat162 p;
                p.x = h0; p.y = h1; *reinterpret_cast<__nv_bfloat162*>(hi + (size_t)r0 * NOUT + col) = p;
                p.x = l0; p.y = l1; *reinterpret_cast<__nv_bfloat162*>(lo + (size_t)r0 * NOUT + col) = p;
                p.x = h2; p.y = h3; *reinterpret_cast<__nv_bfloat162*>(hi + (size_t)r1 * NOUT + col) = p;
                p.x = l2; p.y = l3; *reinterpret_cast<__nv_bfloat162*>(lo + (size_t)r1 * NOUT + col) = p;
            } else {
                float2 q;
                q.x = v0; q.y = v1; *reinterpret_cast<float2*>(outf + (size_t)r0 * NOUT + col) = q;
                q.x = v2; q.y = v3; *reinterpret_cast<float2*>(outf + (size_t)r1 * NOUT + col) = q;
            }
        }
    }
}

#define SMEM_MMA_128 (DEPTH * (16384 + 128 * 128))
#define SMEM_MMA_256 (DEPTH * (16384 + 256 * 128))

// ======================= SIMT GEMM (modes 1 and 2) =======================
#define BM 128
#define BN 128
#define BK 8

template<int MODE>
__global__ __launch_bounds__(256, 2)
void gemm_tpl(const float* __restrict__ A, int lda,
              const float* __restrict__ G,
              const float* __restrict__ Vin, int ldv,
              const float* __restrict__ Sin, int lds_,
              const float* __restrict__ B,
              float* __restrict__ C, int ldc,
              int K, int M, float scale)
{
    __shared__ float As[BK][BM];
    __shared__ float Bs[BK][BN];

    const int tid  = threadIdx.x;
    const int row0 = blockIdx.y * BM;
    const int col0 = blockIdx.x * BN;
    const int c    = (MODE == 2) ? blockIdx.z : 0;

    const int ar = tid >> 1;
    const int ak = (tid & 1) * 4;
    const int br = tid >> 5;
    const int bc = (tid & 31) * 4;
    const int tx = tid & 15;
    const int ty = tid >> 4;

    float acc[8][8];
#pragma unroll
    for (int i = 0; i < 8; i++)
#pragma unroll
        for (int j = 0; j < 8; j++) acc[i][j] = 0.0f;

    const int arow = row0 + ar;

    for (int k0 = 0; k0 < K; k0 += BK) {
        float a[4];
        const int kk0 = k0 + ak;
        if (MODE == 1) {
            float4 av = *(const float4*)(A + (size_t)arow * lda + kk0);
            float4 gv = *(const float4*)(G + (size_t)arow * 768 + kk0);
            a[0] = av.x * gv.x; a[1] = av.y * gv.y;
            a[2] = av.z * gv.z; a[3] = av.w * gv.w;
        } else {
            const float* grow = G + (size_t)arow * 768 + 384;
#pragma unroll
            for (int q = 0; q < 4; q++) {
                int m = kk0 + q;
                float base;
                if (m < 128) {
                    base = Vin[(size_t)arow * ldv + m * 3 + c];
                } else {
                    int mm = m - 128;
                    base = Sin[(size_t)arow * lds_ + mm] *
                           Vin[(size_t)arow * ldv + mm * 3 + c];
                }
                a[q] = grow[m] * base;
            }
        }
        float4 bv = *(const float4*)(B + (size_t)(k0 + br) * M + col0 + bc);

        __syncthreads();
        As[ak + 0][ar] = a[0];
        As[ak + 1][ar] = a[1];
        As[ak + 2][ar] = a[2];
        As[ak + 3][ar] = a[3];
        *(float4*)&Bs[br][bc] = bv;
        __syncthreads();

#pragma unroll
        for (int kk = 0; kk < BK; kk++) {
            float ra[8], rb[8];
            float4 a0 = *(const float4*)&As[kk][ty * 8];
            float4 a1 = *(const float4*)&As[kk][ty * 8 + 4];
            ra[0]=a0.x; ra[1]=a0.y; ra[2]=a0.z; ra[3]=a0.w;
            ra[4]=a1.x; ra[5]=a1.y; ra[6]=a1.z; ra[7]=a1.w;
            float4 b0 = *(const float4*)&Bs[kk][tx * 4];
            float4 b1 = *(const float4*)&Bs[kk][64 + tx * 4];
            rb[0]=b0.x; rb[1]=b0.y; rb[2]=b0.z; rb[3]=b0.w;
            rb[4]=b1.x; rb[5]=b1.y; rb[6]=b1.z; rb[7]=b1.w;
#pragma unroll
            for (int i = 0; i < 8; i++)
#pragma unroll
                for (int j = 0; j < 8; j++)
                    acc[i][j] = fmaf(ra[i], rb[j], acc[i][j]);
        }
    }

#pragma unroll
    for (int i = 0; i < 8; i++) {
        const int r = row0 + ty * 8 + i;
        if (MODE == 1) {
            float4 s0 = *(const float4*)(Sin + (size_t)r * lds_ + col0 + tx * 4);
            float4 s1 = *(const float4*)(Sin + (size_t)r * lds_ + col0 + 64 + tx * 4);
            float4 o0, o1;
            o0.x = s0.x + acc[i][0]*scale; o0.y = s0.y + acc[i][1]*scale;
            o0.z = s0.z + acc[i][2]*scale; o0.w = s0.w + acc[i][3]*scale;
            o1.x = s1.x + acc[i][4]*scale; o1.y = s1.y + acc[i][5]*scale;
            o1.z = s1.z + acc[i][6]*scale; o1.w = s1.w + acc[i][7]*scale;
            *(float4*)(C + (size_t)r * ldc + col0 + tx * 4)      = o0;
            *(float4*)(C + (size_t)r * ldc + col0 + 64 + tx * 4) = o1;
        } else {
#pragma unroll
            for (int j = 0; j < 8; j++) {
                int cc = col0 + tx * 4 + (j & 3) + (j >> 2) * 64;
                float res = Vin[(size_t)r * ldv + cc * 3 + c];
                C[(size_t)r * ldc + cc * 3 + c] = res + acc[i][j] * scale;
            }
        }
    }
}

// ======================= equivariant layernorm =======================
__device__ __forceinline__ float block_sum_128(float x, float* red)
{
#pragma unroll
    for (int o = 16; o; o >>= 1) x += __shfl_xor_sync(0xffffffffu, x, o);
    int t = threadIdx.x;
    if ((t & 31) == 0) red[t >> 5] = x;
    __syncthreads();
    float tot = red[0] + red[1] + red[2] + red[3];
    __syncthreads();
    return tot;
}

__global__ void ln_kernel(float* __restrict__ s, float* __restrict__ v)
{
    __shared__ float red[4];
    int n = blockIdx.x;
    int t = threadIdx.x;

    float sv = s[(size_t)n * 128 + t];
    float* vr = v + (size_t)n * 384 + 3 * t;
    float vx = vr[0], vy = vr[1], vz = vr[2];

    float sum  = block_sum_128(sv, red);
    float sum2 = block_sum_128(sv * sv, red);
    float vsum = block_sum_128(vx*vx + vy*vy + vz*vz, red);

    float mu  = sum * (1.0f / 128.0f);
    float var = sum2 * (1.0f / 128.0f) - mu * mu;
    float inv_sd = rsqrtf(var + 1e-6f);
    s[(size_t)n * 128 + t] = (sv - mu) * inv_sd;

    float inv_vs = rsqrtf(vsum * (1.0f / 384.0f) + 1e-6f);
    vr[0] = vx * inv_vs;
    vr[1] = vy * inv_vs;
    vr[2] = vz * inv_vs;
}

// ======================= launcher =======================
extern "C" void kernel_launch(void* const* d_in, const int* in_sizes, int n_in,
                              void* d_out, int out_size)
{
    const float* x    = (const float*)d_in[0];
    const float* W1_0 = (const float*)d_in[3];
    const float* W2_0 = (const float*)d_in[4];
    const float* Ws_0 = (const float*)d_in[5];
    const float* Wv_0 = (const float*)d_in[6];
    const float* W1_1 = (const float*)d_in[7];
    const float* W2_1 = (const float*)d_in[8];
    const float* Ws_1 = (const float*)d_in[9];
    const float* Wv_1 = (const float*)d_in[10];
    float* out = (float*)d_out;

    static float *scal = nullptr, *g = nullptr, *s = nullptr, *v = nullptr;
    static __nv_bfloat16 *scal_pl = nullptr, *h_pl = nullptr;
    static __nv_bfloat16 *w1t0 = nullptr, *w2t0 = nullptr, *w1t1 = nullptr, *w2t1 = nullptr;
    if (!scal) {
        cudaGetSymbolAddress((void**)&scal,    g_scal);
        cudaGetSymbolAddress((void**)&scal_pl, g_scal_pl);
        cudaGetSymbolAddress((void**)&h_pl,    g_h_pl);
        cudaGetSymbolAddress((void**)&g,       g_g);
        cudaGetSymbolAddress((void**)&s,       g_s);
        cudaGetSymbolAddress((void**)&v,       g_v);
        cudaGetSymbolAddress((void**)&w1t0,    g_w1t0);
        cudaGetSymbolAddress((void**)&w2t0,    g_w2t0);
        cudaGetSymbolAddress((void**)&w1t1,    g_w1t1);
        cudaGetSymbolAddress((void**)&w2t1,    g_w2t1);
        cudaFuncSetAttribute((const void*)gemm_mma<128,0>, cudaFuncAttributeMaxDynamicSharedMemorySize, SMEM_MMA_128);
        cudaFuncSetAttribute((const void*)gemm_mma<256,1>, cudaFuncAttributeMaxDynamicSharedMemorySize, SMEM_MMA_256);
    }

    const float SC384 = 0.051031036307982884f;  // 1/sqrt(384)
    const float SC256 = 0.0625f;                // 1/sqrt(256)
    const int   RB    = N_ROWS / 128;           // 512 row tiles
    const size_t PLS  = (size_t)N_ROWS * 384;   // activation plane stride

    // weight prep (tiny)
    prep_w<<<(384*384 + 255)/256, 256>>>(W1_0, 384, 384, w1t0);
    prep_w<<<(384*768 + 255)/256, 256>>>(W2_0, 384, 768, w2t0);
    prep_w<<<(384*384 + 255)/256, 256>>>(W1_1, 384, 384, w1t1);
    prep_w<<<(384*768 + 255)/256, 256>>>(W2_1, 384, 768, w2t1);

    // ================= block 0 =================
    build_scal2<<<N_ROWS * 128 / 256, 256>>>(x, 512, x + 128, 512, scal, scal_pl);
    gemm_mma<128,0><<<dim3(3, RB), 256, SMEM_MMA_128>>>(scal_pl, PLS, w1t0, (size_t)384*384,
                                                        nullptr, h_pl, PLS, 384, 384, SC384);
    gemm_mma<256,1><<<dim3(3, RB), 256, SMEM_MMA_256>>>(h_pl, PLS, w2t0, (size_t)384*768,
                                                        g, nullptr, 0, 384, 768, SC384);
    gemm_tpl<1><<<dim3(1, RB), 256>>>(scal, 384, g, nullptr, 0, x, 512,
                                      Ws_0, s, 128, 384, 128, SC384);
    gemm_tpl<2><<<dim3(1, RB, 3), 256>>>(nullptr, 0, g, x + 128, 512, x, 512,
                                         Wv_0, v, 384, 256, 128, SC256);
    ln_kernel<<<N_ROWS, 128>>>(s, v);

    // ================= block 1 =================
    build_scal2<<<N_ROWS * 128 / 256, 256>>>(s, 128, v, 384, scal, scal_pl);
    gemm_mma<128,0><<<dim3(3, RB), 256, SMEM_MMA_128>>>(scal_pl, PLS, w1t1, (size_t)384*384,
                                                        nullptr, h_pl, PLS, 384, 384, SC384);
    gemm_mma<256,1><<<dim3(3, RB), 256, SMEM_MMA_256>>>(h_pl, PLS, w2t1, (size_t)384*768,
                                                        g, nullptr, 0, 384, 768, SC384);
    gemm_tpl<1><<<dim3(1, RB), 256>>>(scal, 384, g, nullptr, 0, s, 128,
                                      Ws_1, out, 512, 384, 128, SC384);
    gemm_tpl<2><<<dim3(1, RB, 3), 256>>>(nullptr, 0, g, v, 384, s, 128,
                                         Wv_1, out + 128, 512, 256, 128, SC256);
}

// round 11
// speedup vs baseline: 1.3811x; 1.0029x over previous
#include <cuda_runtime.h>
#include <cuda_bf16.h>
#include <cstdint>
#include <math.h>

#define N_ROWS 65536

// ======================= scratch (device globals) =======================
__device__ float         g_scal[(size_t)N_ROWS * 384];
__device__ __nv_bfloat16 g_scal_pl[2 * (size_t)N_ROWS * 384];   // hi/lo planes
__device__ __nv_bfloat16 g_h_pl[2 * (size_t)N_ROWS * 384];
__device__ float         g_g[(size_t)N_ROWS * 768];
__device__ float         g_s[(size_t)N_ROWS * 128];
__device__ float         g_v[(size_t)N_ROWS * 384];
__device__ __nv_bfloat16 g_w1t0[2 * 384 * 384];                 // [N,K] hi/lo planes
__device__ __nv_bfloat16 g_w2t0[2 * 384 * 768];
__device__ __nv_bfloat16 g_w1t1[2 * 384 * 384];
__device__ __nv_bfloat16 g_w2t1[2 * 384 * 768];

__device__ __forceinline__ float silu_f(float x) {
    return x / (1.0f + __expf(-x));
}
__device__ __forceinline__ void split_bf16(float x, __nv_bfloat16& hi, __nv_bfloat16& lo) {
    hi = __float2bfloat16(x);
    lo = __float2bfloat16(x - __bfloat162float(hi));
}

// ======================= PTX helpers (sm_100-baseline only) =======================
__device__ __forceinline__ uint32_t smem_u32(const void* p) {
    uint32_t a;
    asm("{ .reg .u64 t; cvta.to.shared.u64 t, %1; cvt.u32.u64 %0, t; }" : "=r"(a) : "l"(p));
    return a;
}
__device__ __forceinline__ void cp16(uint32_t dst, const void* src) {
    asm volatile("cp.async.cg.shared.global [%0], [%1], 16;" :: "r"(dst), "l"(src));
}
#define CP_COMMIT() asm volatile("cp.async.commit_group;" ::: "memory")
template<int NWAIT> __device__ __forceinline__ void cp_wait() {
    asm volatile("cp.async.wait_group %0;" :: "n"(NWAIT) : "memory");
}
__device__ __forceinline__ void ldsm_x4(uint32_t (&r)[4], uint32_t addr) {
    asm volatile("ldmatrix.sync.aligned.m8n8.x4.shared.b16 {%0,%1,%2,%3}, [%4];"
                 : "=r"(r[0]), "=r"(r[1]), "=r"(r[2]), "=r"(r[3]) : "r"(addr));
}
__device__ __forceinline__ void mma_bf16(float (&d)[4], const uint32_t (&a)[4],
                                         uint32_t b0, uint32_t b1) {
    asm volatile("mma.sync.aligned.m16n8k16.row.col.f32.bf16.bf16.f32 "
                 "{%0,%1,%2,%3}, {%4,%5,%6,%7}, {%8,%9}, {%0,%1,%2,%3};"
                 : "+f"(d[0]), "+f"(d[1]), "+f"(d[2]), "+f"(d[3])
                 : "r"(a[0]), "r"(a[1]), "r"(a[2]), "r"(a[3]), "r"(b0), "r"(b1));
}

// ======================= weight prep: fp32 [K,N] -> bf16 hi/lo planes [N,K] =======================
__global__ void prep_w(const float* __restrict__ W, int Kd, int Nd, __nv_bfloat16* __restrict__ out) {
    int idx = blockIdx.x * blockDim.x + threadIdx.x;
    if (idx >= Kd * Nd) return;
    int k = idx / Nd, n = idx % Nd;
    __nv_bfloat16 hi, lo;
    split_bf16(W[idx], hi, lo);
    out[(size_t)n * Kd + k] = hi;
    out[(size_t)Kd * Nd + (size_t)n * Kd + k] = lo;
}

// ======================= build scal (fp32 + planes) =======================
__global__ void build_scal2(const float* __restrict__ sp, int ss,
                            const float* __restrict__ vp, int vs,
                            float* __restrict__ scal, __nv_bfloat16* __restrict__ spl)
{
    const size_t PLS = (size_t)N_ROWS * 384;
    int idx = blockIdx.x * blockDim.x + threadIdx.x;
    int n = idx >> 7;
    int j = idx & 127;
    float s = sp[(size_t)n * ss + j];
    const float* vr = vp + (size_t)n * vs + 3 * j;
    float vx = vr[0], vy = vr[1], vz = vr[2];
    float vals[3];
    vals[0] = s;
    vals[1] = s * s;
    vals[2] = (vx*vx + vy*vy + vz*vz) * 0.5773502691896258f;
    float* row = scal + (size_t)n * 384;
    __nv_bfloat16* prow = spl + (size_t)n * 384;
#pragma unroll
    for (int q = 0; q < 3; q++) {
        int col = q * 128 + j;
        row[col] = vals[q];
        __nv_bfloat16 hi, lo;
        split_bf16(vals[q], hi, lo);
        prow[col] = hi;
        prow[PLS + col] = lo;
    }
}

// ======================= mma.sync bf16 split GEMM =======================
// C[row0:+128, n0:+TILE_N] = silu(scale * sum_3passes(Apl @ Wpl^T))
// 8 warps (2x4), warp tile 64 x TILE_N/4, k-slab 64 bf16, 4-stage cp.async ring
// with 3 chunks in flight (wait_group<2>). SMEM rows 128B, XOR-16B swizzle on
// row index; unified coalesced loader (consecutive threads -> consecutive 16B).
// OMODE 0: write bf16 hi/lo planes.  OMODE 1: write fp32.
#define DEPTH 4

template<int TILE_N, int OMODE>
__global__ void __launch_bounds__(256, 1)
gemm_mma(const __nv_bfloat16* __restrict__ Apl, size_t a_ps,
         const __nv_bfloat16* __restrict__ Wpl, size_t w_ps,
         float* __restrict__ outf, __nv_bfloat16* __restrict__ outpl, size_t out_ps,
         int K, int NOUT, float scale)
{
    constexpr int NJ    = TILE_N / 32;          // 8-col groups per warp (4 or 8)
    constexpr int PI    = TILE_N / 64;          // B ldsm_x4 per ks (2 or 4)
    constexpr int STAGE = 16384 + TILE_N * 128; // bytes per stage
    constexpr int ROWS  = 128 + TILE_N;         // smem rows per stage
    constexpr int OPS   = ROWS * 8 / 256;       // cp16 per thread per chunk

    extern __shared__ __align__(1024) char smem[];
    const uint32_t sb = smem_u32(smem);
    const int tid    = threadIdx.x;
    const int lane   = tid & 31;
    const int wid    = tid >> 5;
    const int warp_m = wid >> 2;        // 0..1
    const int warp_n = wid & 3;         // 0..3
    const int row0   = blockIdx.y * 128;
    const int n0     = blockIdx.x * TILE_N;
    const int KC     = K / 64;          // chunks per pass (6)
    const int P      = 3 * KC;          // total chunks (18)
    const size_t rowbytes = (size_t)K * 2;

    float acc[4][NJ][4];
#pragma unroll
    for (int i = 0; i < 4; i++)
#pragma unroll
        for (int j = 0; j < NJ; j++)
#pragma unroll
            for (int q = 0; q < 4; q++) acc[i][j][q] = 0.0f;

    auto issue_chunk = [&](int c) {
        int pass = c / KC, kc = c - pass * KC;
        uint32_t st = sb + (uint32_t)(c % DEPTH) * STAGE;
        const char* Abase = (const char*)(Apl + (pass == 2 ? a_ps : 0))
                          + (size_t)row0 * rowbytes + (size_t)kc * 128;
        const char* Wbase = (const char*)(Wpl + (pass == 1 ? w_ps : 0))
                          + (size_t)n0 * rowbytes + (size_t)kc * 128;
#pragma unroll
        for (int j = 0; j < OPS; j++) {
            int o    = tid + 256 * j;
            int row  = o >> 3;
            int colb = (o & 7) * 16;
            uint32_t sw = (uint32_t)(colb ^ ((row & 7) << 4));
            const char* src = (row < 128)
                ? Abase + (size_t)row * rowbytes + colb
                : Wbase + (size_t)(row - 128) * rowbytes + colb;
            cp16(st + (uint32_t)row * 128u + sw, src);
        }
    };

    issue_chunk(0); CP_COMMIT();
    issue_chunk(1); CP_COMMIT();
    issue_chunk(2); CP_COMMIT();

    const uint32_t khalf = ((uint32_t)(lane >> 4)) << 4;   // 0 or 16

    for (int c = 0; c < P; c++) {
        cp_wait<2>();                    // FIFO: chunk c landed (mine)
        __syncthreads();                 // all threads: chunk c visible; compute c-1 done
        if (c + 3 < P) issue_chunk(c + 3);
        CP_COMMIT();                     // commit every iter -> stable group indexing

        const uint32_t stA = sb + (uint32_t)(c % DEPTH) * STAGE;
        const uint32_t stB = stA + 16384u;

#pragma unroll
        for (int ks = 0; ks < 4; ks++) {
            const uint32_t kb = (uint32_t)ks * 32u + khalf;
            uint32_t a[4][4];
#pragma unroll
            for (int mi = 0; mi < 4; mi++) {
                uint32_t row  = (uint32_t)(warp_m * 64 + mi * 16 + (lane & 15));
                uint32_t addr = stA + row * 128u + (kb ^ ((row & 7) << 4));
                ldsm_x4(a[mi], addr);
            }
            uint32_t b[PI][4];
#pragma unroll
            for (int pi = 0; pi < PI; pi++) {
                uint32_t row  = (uint32_t)(warp_n * (TILE_N / 4) + pi * 16 + (lane & 15));
                uint32_t addr = stB + row * 128u + (kb ^ ((row & 7) << 4));
                ldsm_x4(b[pi], addr);
            }
#pragma unroll
            for (int mi = 0; mi < 4; mi++)
#pragma unroll
                for (int nj = 0; nj < NJ; nj++)
                    mma_bf16(acc[mi][nj], a[mi], b[nj >> 1][nj & 1], b[nj >> 1][(nj & 1) + 2]);
        }
    }

    // ---- epilogue ----
    const int rbase = row0 + warp_m * 64 + (lane >> 2);
    const int cbase = n0 + warp_n * (TILE_N / 4) + (lane & 3) * 2;
#pragma unroll
    for (int mi = 0; mi < 4; mi++) {
#pragma unroll
        for (int nj = 0; nj < NJ; nj++) {
            const int col = cbase + nj * 8;
            const int r0  = rbase + mi * 16;
            const int r1  = r0 + 8;
            float v0 = silu_f(acc[mi][nj][0] * scale);
            float v1 = silu_f(acc[mi][nj][1] * scale);
            float v2 = silu_f(acc[mi][nj][2] * scale);
            float v3 = silu_f(acc[mi][nj][3] * scale);
            if (OMODE == 0) {
                __nv_bfloat16 h0, l0, h1, l1, h2, l2, h3, l3;
                split_bf16(v0, h0, l0); split_bf16(v1, h1, l1);
                split_bf16(v2, h2, l2); split_bf16(v3, h3, l3);
                __nv_bfloat16* hi = outpl;
                __nv_bfloat16* lo = outpl + out_ps;
                __nv_bfloat162 p;
                p.x = h0; p.y = h1; *reinterpret_cast<__nv_bfloat162*>(hi + (size_t)r0 * NOUT + col) = p;
                p.x = l0; p.y = l1; *reinterpret_cast<__nv_bfloat162*>(lo + (size_t)r0 * NOUT + col) = p;
                p.x = h2; p.y = h3; *reinterpret_cast<__nv_bfloat162*>(hi + (size_t)r1 * NOUT + col) = p;
                p.x = l2; p.y = l3; *reinterpret_cast<__nv_bfloat162*>(lo + (size_t)r1 * NOUT + col) = p;
            } else {
                float2 q;
                q.x = v0; q.y = v1; *reinterpret_cast<float2*>(outf + (size_t)r0 * NOUT + col) = q;
                q.x = v2; q.y = v3; *reinterpret_cast<float2*>(outf + (size_t)r1 * NOUT + col) = q;
            }
        }
    }
}

#define SMEM_MMA_128 (DEPTH * (16384 + 128 * 128))
#define SMEM_MMA_256 (DEPTH * (16384 + 256 * 128))

// ======================= SIMT GEMM (modes 1 and 2) =======================
#define BM 128
#define BN 128
#define BK 8

template<int MODE>
__global__ __launch_bounds__(256, 2)
void gemm_tpl(const float* __restrict__ A, int lda,
              const float* __restrict__ G,
              const float* __restrict__ Vin, int ldv,
              const float* __restrict__ Sin, int lds_,
              const float* __restrict__ B,
              float* __restrict__ C, int ldc,
              int K, int M, float scale)
{
    __shared__ float As[BK][BM];
    __shared__ float Bs[BK][BN];

    const int tid  = threadIdx.x;
    const int row0 = blockIdx.y * BM;
    const int col0 = blockIdx.x * BN;
    const int c    = (MODE == 2) ? blockIdx.z : 0;

    const int ar = tid >> 1;
    const int ak = (tid & 1) * 4;
    const int br = tid >> 5;
    const int bc = (tid & 31) * 4;
    const int tx = tid & 15;
    const int ty = tid >> 4;

    float acc[8][8];
#pragma unroll
    for (int i = 0; i < 8; i++)
#pragma unroll
        for (int j = 0; j < 8; j++) acc[i][j] = 0.0f;

    const int arow = row0 + ar;

    for (int k0 = 0; k0 < K; k0 += BK) {
        float a[4];
        const int kk0 = k0 + ak;
        if (MODE == 1) {
            float4 av = *(const float4*)(A + (size_t)arow * lda + kk0);
            float4 gv = *(const float4*)(G + (size_t)arow * 768 + kk0);
            a[0] = av.x * gv.x; a[1] = av.y * gv.y;
            a[2] = av.z * gv.z; a[3] = av.w * gv.w;
        } else {
            const float* grow = G + (size_t)arow * 768 + 384;
#pragma unroll
            for (int q = 0; q < 4; q++) {
                int m = kk0 + q;
                float base;
                if (m < 128) {
                    base = Vin[(size_t)arow * ldv + m * 3 + c];
                } else {
                    int mm = m - 128;
                    base = Sin[(size_t)arow * lds_ + mm] *
                           Vin[(size_t)arow * ldv + mm * 3 + c];
                }
                a[q] = grow[m] * base;
            }
        }
        float4 bv = *(const float4*)(B + (size_t)(k0 + br) * M + col0 + bc);

        __syncthreads();
        As[ak + 0][ar] = a[0];
        As[ak + 1][ar] = a[1];
        As[ak + 2][ar] = a[2];
        As[ak + 3][ar] = a[3];
        *(float4*)&Bs[br][bc] = bv;
        __syncthreads();

#pragma unroll
        for (int kk = 0; kk < BK; kk++) {
            float ra[8], rb[8];
            float4 a0 = *(const float4*)&As[kk][ty * 8];
            float4 a1 = *(const float4*)&As[kk][ty * 8 + 4];
            ra[0]=a0.x; ra[1]=a0.y; ra[2]=a0.z; ra[3]=a0.w;
            ra[4]=a1.x; ra[5]=a1.y; ra[6]=a1.z; ra[7]=a1.w;
            float4 b0 = *(const float4*)&Bs[kk][tx * 4];
            float4 b1 = *(const float4*)&Bs[kk][64 + tx * 4];
            rb[0]=b0.x; rb[1]=b0.y; rb[2]=b0.z; rb[3]=b0.w;
            rb[4]=b1.x; rb[5]=b1.y; rb[6]=b1.z; rb[7]=b1.w;
#pragma unroll
            for (int i = 0; i < 8; i++)
#pragma unroll
                for (int j = 0; j < 8; j++)
                    acc[i][j] = fmaf(ra[i], rb[j], acc[i][j]);
        }
    }

#pragma unroll
    for (int i = 0; i < 8; i++) {
        const int r = row0 + ty * 8 + i;
        if (MODE == 1) {
            float4 s0 = *(const float4*)(Sin + (size_t)r * lds_ + col0 + tx * 4);
            float4 s1 = *(const float4*)(Sin + (size_t)r * lds_ + col0 + 64 + tx * 4);
            float4 o0, o1;
            o0.x = s0.x + acc[i][0]*scale; o0.y = s0.y + acc[i][1]*scale;
            o0.z = s0.z + acc[i][2]*scale; o0.w = s0.w + acc[i][3]*scale;
            o1.x = s1.x + acc[i][4]*scale; o1.y = s1.y + acc[i][5]*scale;
            o1.z = s1.z + acc[i][6]*scale; o1.w = s1.w + acc[i][7]*scale;
            *(float4*)(C + (size_t)r * ldc + col0 + tx * 4)      = o0;
            *(float4*)(C + (size_t)r * ldc + col0 + 64 + tx * 4) = o1;
        } else {
#pragma unroll
            for (int j = 0; j < 8; j++) {
                int cc = col0 + tx * 4 + (j & 3) + (j >> 2) * 64;
                float res = Vin[(size_t)r * ldv + cc * 3 + c];
                C[(size_t)r * ldc + cc * 3 + c] = res + acc[i][j] * scale;
            }
        }
    }
}

// ======================= equivariant layernorm =======================
__device__ __forceinline__ float block_sum_128(float x, float* red)
{
#pragma unroll
    for (int o = 16; o; o >>= 1) x += __shfl_xor_sync(0xffffffffu, x, o);
    int t = threadIdx.x;
    if ((t & 31) == 0) red[t >> 5] = x;
    __syncthreads();
    float tot = red[0] + red[1] + red[2] + red[3];
    __syncthreads();
    return tot;
}

__global__ void ln_kernel(float* __restrict__ s, float* __restrict__ v)
{
    __shared__ float red[4];
    int n = blockIdx.x;
    int t = threadIdx.x;

    float sv = s[(size_t)n * 128 + t];
    float* vr = v + (size_t)n * 384 + 3 * t;
    float vx = vr[0], vy = vr[1], vz = vr[2];

    float sum  = block_sum_128(sv, red);
    float sum2 = block_sum_128(sv * sv, red);
    float vsum = block_sum_128(vx*vx + vy*vy + vz*vz, red);

    float mu  = sum * (1.0f / 128.0f);
    float var = sum2 * (1.0f / 128.0f) - mu * mu;
    float inv_sd = rsqrtf(var + 1e-6f);
    s[(size_t)n * 128 + t] = (sv - mu) * inv_sd;

    float inv_vs = rsqrtf(vsum * (1.0f / 384.0f) + 1e-6f);
    vr[0] = vx * inv_vs;
    vr[1] = vy * inv_vs;
    vr[2] = vz * inv_vs;
}

// ======================= launcher =======================
extern "C" void kernel_launch(void* const* d_in, const int* in_sizes, int n_in,
                              void* d_out, int out_size)
{
    const float* x    = (const float*)d_in[0];
    const float* W1_0 = (const float*)d_in[3];
    const float* W2_0 = (const float*)d_in[4];
    const float* Ws_0 = (const float*)d_in[5];
    const float* Wv_0 = (const float*)d_in[6];
    const float* W1_1 = (const float*)d_in[7];
    const float* W2_1 = (const float*)d_in[8];
    const float* Ws_1 = (const float*)d_in[9];
    const float* Wv_1 = (const float*)d_in[10];
    float* out = (float*)d_out;

    static float *scal = nullptr, *g = nullptr, *s = nullptr, *v = nullptr;
    static __nv_bfloat16 *scal_pl = nullptr, *h_pl = nullptr;
    static __nv_bfloat16 *w1t0 = nullptr, *w2t0 = nullptr, *w1t1 = nullptr, *w2t1 = nullptr;
    if (!scal) {
        cudaGetSymbolAddress((void**)&scal,    g_scal);
        cudaGetSymbolAddress((void**)&scal_pl, g_scal_pl);
        cudaGetSymbolAddress((void**)&h_pl,    g_h_pl);
        cudaGetSymbolAddress((void**)&g,       g_g);
        cudaGetSymbolAddress((void**)&s,       g_s);
        cudaGetSymbolAddress((void**)&v,       g_v);
        cudaGetSymbolAddress((void**)&w1t0,    g_w1t0);
        cudaGetSymbolAddress((void**)&w2t0,    g_w2t0);
        cudaGetSymbolAddress((void**)&w1t1,    g_w1t1);
        cudaGetSymbolAddress((void**)&w2t1,    g_w2t1);
        cudaFuncSetAttribute((const void*)gemm_mma<128,0>, cudaFuncAttributeMaxDynamicSharedMemorySize, SMEM_MMA_128);
        cudaFuncSetAttribute((const void*)gemm_mma<256,1>, cudaFuncAttributeMaxDynamicSharedMemorySize, SMEM_MMA_256);
    }

    const float SC384 = 0.051031036307982884f;  // 1/sqrt(384)
    const float SC256 = 0.0625f;                // 1/sqrt(256)
    const int   RB    = N_ROWS / 128;           // 512 row tiles
    const size_t PLS  = (size_t)N_ROWS * 384;   // activation plane stride

    // weight prep (tiny)
    prep_w<<<(384*384 + 255)/256, 256>>>(W1_0, 384, 384, w1t0);
    prep_w<<<(384*768 + 255)/256, 256>>>(W2_0, 384, 768, w2t0);
    prep_w<<<(384*384 + 255)/256, 256>>>(W1_1, 384, 384, w1t1);
    prep_w<<<(384*768 + 255)/256, 256>>>(W2_1, 384, 768, w2t1);

    // ================= block 0 =================
    build_scal2<<<N_ROWS * 128 / 256, 256>>>(x, 512, x + 128, 512, scal, scal_pl);
    gemm_mma<128,0><<<dim3(3, RB), 256, SMEM_MMA_128>>>(scal_pl, PLS, w1t0, (size_t)384*384,
                                                        nullptr, h_pl, PLS, 384, 384, SC384);
    gemm_mma<256,1><<<dim3(3, RB), 256, SMEM_MMA_256>>>(h_pl, PLS, w2t0, (size_t)384*768,
                                                        g, nullptr, 0, 384, 768, SC384);
    gemm_tpl<1><<<dim3(1, RB), 256>>>(scal, 384, g, nullptr, 0, x, 512,
                                      Ws_0, s, 128, 384, 128, SC384);
    gemm_tpl<2><<<dim3(1, RB, 3), 256>>>(nullptr, 0, g, x + 128, 512, x, 512,
                                         Wv_0, v, 384, 256, 128, SC256);
    ln_kernel<<<N_ROWS, 128>>>(s, v);

    // ================= block 1 =================
    build_scal2<<<N_ROWS * 128 / 256, 256>>>(s, 128, v, 384, scal, scal_pl);
    gemm_mma<128,0><<<dim3(3, RB), 256, SMEM_MMA_128>>>(scal_pl, PLS, w1t1, (size_t)384*384,
                                                        nullptr, h_pl, PLS, 384, 384, SC384);
    gemm_mma<256,1><<<dim3(3, RB), 256, SMEM_MMA_256>>>(h_pl, PLS, w2t1, (size_t)384*768,
                                                        g, nullptr, 0, 384, 768, SC384);
    gemm_tpl<1><<<dim3(1, RB), 256>>>(scal, 384, g, nullptr, 0, s, 128,
                                      Ws_1, out, 512, 384, 128, SC384);
    gemm_tpl<2><<<dim3(1, RB, 3), 256>>>(nullptr, 0, g, v, 384, s, 128,
                                         Wv_1, out + 128, 512, 256, 128, SC256);
}